// round 12
// baseline (speedup 1.0000x reference)
#include <cuda_runtime.h>
#include <cstdint>

// MessagePassing: out[row[e]] += x[col[e]]  for e in [0, E)
// x: [N, 32] f32; edge_index: [2, E] int32. row = ei[0:E], col = ei[E:2E].
//
// Converged scatter (R1-R9): edge-parallel, 8 lanes/edge x 16B chunks, NC
// LDG.128 gather + red.global.add.v4.f32; at the ~6300 B/cyc LTS chip cap.
// Fusion v2 (R11 post-mortem: hot-spin poll storm on one LTS slice cost
// ~5us): zero blocks first in the grid; last zero block publishes a
// release flag; scatter blocks take a single-acquire-load fast path
// (all post-wave-1 blocks) or a __nanosleep-backoff poll (wave-1 only),
// then fire REDs. Counter+flag reset each replay via an 8B memset node.

#define D 32
#define U 4
#define ZVEC 4   // float4 stores per zero-block thread

__device__ unsigned g_zero_sync[2];   // [0] = block counter, [1] = done flag

__device__ __forceinline__ void red_add_v4(float* dst, float4 v) {
    asm volatile("red.global.add.v4.f32 [%0], {%1, %2, %3, %4};"
                 :: "l"(dst), "f"(v.x), "f"(v.y), "f"(v.z), "f"(v.w)
                 : "memory");
}

__global__ __launch_bounds__(256) void mp_fused_kernel(
        const float* __restrict__ x,
        const int* __restrict__ ei,
        float* __restrict__ out,
        int E, int ngroups, int n4, int ZB) {
    int bid = blockIdx.x;

    if (bid < ZB) {
        // ---- zero phase: block zeroes 256*ZVEC float4s ----
        float4 z = make_float4(0.f, 0.f, 0.f, 0.f);
        int base = bid * (256 * ZVEC) + threadIdx.x;
        #pragma unroll
        for (int i = 0; i < ZVEC; i++) {
            int idx = base + i * 256;
            if (idx < n4) reinterpret_cast<float4*>(out)[idx] = z;
        }
        __threadfence();
        __syncthreads();
        if (threadIdx.x == 0) {
            unsigned prev = atomicAdd(&g_zero_sync[0], 1u);
            if (prev == (unsigned)(ZB - 1)) {
                // last zero block: publish completion
                asm volatile("st.release.gpu.global.u32 [%0], %1;"
                             :: "l"(&g_zero_sync[1]), "r"(1u) : "memory");
            }
        }
        return;
    }

    // ---- scatter phase ----
    int t = (bid - ZB) * 256 + threadIdx.x;
    int g = t >> 3;                 // edge-group id: edges [g*U, g*U+U)
    int chunk = (t & 7) << 2;       // float offset within the 32-float row
    bool active = (g < ngroups);

    int r[U], c[U];
    float4 v[U];
    if (active) {
        int e0 = g * U;
        int4 rows = __ldg(reinterpret_cast<const int4*>(ei + e0));
        int4 cols = __ldg(reinterpret_cast<const int4*>(ei + E + e0));
        r[0] = rows.x; r[1] = rows.y; r[2] = rows.z; r[3] = rows.w;
        c[0] = cols.x; c[1] = cols.y; c[2] = cols.z; c[3] = cols.w;
        #pragma unroll
        for (int i = 0; i < U; i++)
            v[i] = __ldg(reinterpret_cast<const float4*>(
                       x + (long long)c[i] * D + chunk));
    }

    // wait until the zero phase has published (fast path: one acquire load)
    if (threadIdx.x == 0) {
        unsigned done;
        asm volatile("ld.acquire.gpu.global.u32 %0, [%1];"
                     : "=r"(done) : "l"(&g_zero_sync[1]) : "memory");
        while (!done) {
            __nanosleep(200);
            asm volatile("ld.acquire.gpu.global.u32 %0, [%1];"
                         : "=r"(done) : "l"(&g_zero_sync[1]) : "memory");
        }
    }
    __syncthreads();

    if (active) {
        #pragma unroll
        for (int i = 0; i < U; i++)
            red_add_v4(out + (long long)r[i] * D + chunk, v[i]);
    }
}

// Scalar tail for E % U != 0 (not hit for E = 1.6M; kept for generality).
__global__ void mp_tail_kernel(const float* __restrict__ x,
                               const int* __restrict__ ei,
                               float* __restrict__ out,
                               int Estart, int E) {
    int t = blockIdx.x * blockDim.x + threadIdx.x;
    int e = Estart + (t >> 3);
    if (e >= E) return;
    int chunk = (t & 7) << 2;
    int r = ei[e];
    int c = ei[E + e];
    float4 v = __ldg(reinterpret_cast<const float4*>(
                   x + (long long)c * D + chunk));
    red_add_v4(out + (long long)r * D + chunk, v);
}

extern "C" void kernel_launch(void* const* d_in, const int* in_sizes, int n_in,
                              void* d_out, int out_size) {
    const float* x = (const float*)d_in[0];
    const int* ei = (const int*)d_in[1];
    float* out = (float*)d_out;

    const int E = in_sizes[1] / 2;    // edge_index has 2*E elements
    const int n4 = out_size / 4;      // out: N*32 floats -> N*8 float4

    // reset counter+flag (captured as one memset node; replay-safe)
    void* sync = nullptr;
    cudaGetSymbolAddress(&sync, g_zero_sync);
    cudaMemsetAsync(sync, 0, 2 * sizeof(unsigned), 0);

    int ngroups = E / U;
    int ZB = (n4 + 256 * ZVEC - 1) / (256 * ZVEC);        // zero blocks
    int SB = (int)(((long long)ngroups * 8 + 255) / 256); // scatter blocks
    mp_fused_kernel<<<ZB + SB, 256>>>(x, ei, out, E, ngroups, n4, ZB);

    int tail = E - ngroups * U;
    if (tail > 0)
        mp_tail_kernel<<<(tail * 8 + 255) / 256, 256>>>(x, ei, out,
                                                        ngroups * U, E);
}

// round 13
// speedup vs baseline: 1.1313x; 1.1313x over previous
#include <cuda_runtime.h>
#include <cstdint>

// MessagePassing: out[row[e]] += x[col[e]]  for e in [0, E)
// x: [N, 32] f32; edge_index: [2, E] int32. row = ei[0:E], col = ei[E:2E].
//
// CONVERGED (12 rounds): edge-parallel, 8 lanes per edge x 16B chunks,
// NC LDG.128 gather + red.global.add.v4.f32 scatter, no hot-path branches.
// Scatter = ~423MB LTS traffic in ~37.9us = ~94% of the measured ~6300
// B/cyc B300 LTS chip cap. Rejected with measurements: U=8 / software
// prefetch (occupancy loss), CSR rebuild (build sectors ~= savings), SMEM
// binning (ATOMS 10x worse than LTS atomic ALUs), PDL and two fused
// zero+scatter variants (device-side dependency overhead > ~3us gain).
// This is the R8 record configuration, resubmitted as final.

#define D 32
#define U 4

__device__ __forceinline__ void red_add_v4(float* dst, float4 v) {
    asm volatile("red.global.add.v4.f32 [%0], {%1, %2, %3, %4};"
                 :: "l"(dst), "f"(v.x), "f"(v.y), "f"(v.z), "f"(v.w)
                 : "memory");
}

// Handles full groups only: edges [0, ngroups*U). No branches in hot path.
__global__ __launch_bounds__(256) void mp_scatter_kernel(
        const float* __restrict__ x,
        const int* __restrict__ ei,
        float* __restrict__ out,
        int E, int ngroups) {
    int t = blockIdx.x * blockDim.x + threadIdx.x;
    int g = t >> 3;                 // edge-group id: edges [g*U, g*U+U)
    if (g >= ngroups) return;
    int chunk = (t & 7) << 2;       // float offset within the 32-float row
    int e0 = g * U;

    int4 rows = __ldg(reinterpret_cast<const int4*>(ei + e0));
    int4 cols = __ldg(reinterpret_cast<const int4*>(ei + E + e0));

    int r[U] = {rows.x, rows.y, rows.z, rows.w};
    int c[U] = {cols.x, cols.y, cols.z, cols.w};

    float4 v[U];
    #pragma unroll
    for (int i = 0; i < U; i++)
        v[i] = __ldg(reinterpret_cast<const float4*>(
                   x + (long long)c[i] * D + chunk));

    #pragma unroll
    for (int i = 0; i < U; i++)
        red_add_v4(out + (long long)r[i] * D + chunk, v[i]);
}

// Scalar tail for E % U != 0 (not hit for E = 1.6M; kept for generality).
__global__ void mp_tail_kernel(const float* __restrict__ x,
                               const int* __restrict__ ei,
                               float* __restrict__ out,
                               int Estart, int E) {
    int t = blockIdx.x * blockDim.x + threadIdx.x;
    int e = Estart + (t >> 3);
    if (e >= E) return;
    int chunk = (t & 7) << 2;
    int r = ei[e];
    int c = ei[E + e];
    float4 v = __ldg(reinterpret_cast<const float4*>(
                   x + (long long)c * D + chunk));
    red_add_v4(out + (long long)r * D + chunk, v);
}

extern "C" void kernel_launch(void* const* d_in, const int* in_sizes, int n_in,
                              void* d_out, int out_size) {
    const float* x = (const float*)d_in[0];
    const int* ei = (const int*)d_in[1];
    float* out = (float*)d_out;

    const int E = in_sizes[1] / 2;    // edge_index has 2*E elements

    // 1) zero the output (harness poisons it with 0xAA)
    cudaMemsetAsync(out, 0, (size_t)out_size * sizeof(float), 0);

    // 2) gather + vectorized scatter-add, U edges per 8-lane group
    {
        int ngroups = E / U;
        long long total = (long long)ngroups * 8;
        int threads = 256;
        int blocks = (int)((total + threads - 1) / threads);
        mp_scatter_kernel<<<blocks, threads>>>(x, ei, out, E, ngroups);

        int tail = E - ngroups * U;
        if (tail > 0)
            mp_tail_kernel<<<(tail * 8 + 255) / 256, 256>>>(x, ei, out,
                                                            ngroups * U, E);
    }
}